// round 14
// baseline (speedup 1.0000x reference)
#include <cuda_runtime.h>
#include <cuda_bf16.h>

#define NX 1024
#define NCELL 1023
#define EPSV 1e-10f
#define BLOCK_T 256
#define EVAL_MINBLK 6
#define EVAL_BLOCKS (EVAL_MINBLK * 148)   // one persistent wave at 6 blocks/SM

// Scratch (__device__ globals — allocation-free rule)
__device__ float2 g_cellx[NCELL];           // (x_i, 1/max(dx,EPS)) per cell
__device__ float2 g_celly[NCELL];
__device__ float4 g_quad[(NX - 1) * NX];    // {u00,u10,u01,u11} per cell (ix<<10 | iy)

// ---------------------------------------------------------------------------
// Builder (unchanged)
// ---------------------------------------------------------------------------
__device__ __forceinline__ void build_one_grid(const float* __restrict__ inc,
                                               float2* __restrict__ cells) {
    __shared__ float scum[1024];
    __shared__ float sg[1024];
    __shared__ float swarp[8];

    const int t    = threadIdx.x;       // 0..255
    const int lane = t & 31;
    const int warp = t >> 5;

    float v[4];
    #pragma unroll
    for (int j = 0; j < 4; j++) {
        int idx = 4 * t + j;
        float val = 0.0f;
        if (idx < 1023) {
            float xv = inc[idx];
            float sp = fmaxf(xv, 0.0f) + log1pf(expf(-fabsf(xv)));  // softplus
            val = fmaxf(sp, 1e-6f);
        }
        v[j] = val;
    }
    float c0 = v[0];
    float c1 = c0 + v[1];
    float c2 = c1 + v[2];
    float c3 = c2 + v[3];

    float incl = c3;
    #pragma unroll
    for (int off = 1; off < 32; off <<= 1) {
        float up = __shfl_up_sync(0xffffffff, incl, off);
        if (lane >= off) incl += up;
    }
    float thr_excl = incl - c3;
    if (lane == 31) swarp[warp] = incl;
    __syncthreads();

    if (warp == 0 && lane < 8) {
        float w = swarp[lane];
        #pragma unroll
        for (int off = 1; off < 8; off <<= 1) {
            float up = __shfl_up_sync(0xff, w, off);
            if (lane >= off) w += up;
        }
        swarp[lane] = w - swarp[lane];
    }
    __syncthreads();

    float pref = swarp[warp] + thr_excl;
    scum[4 * t + 0] = pref + c0;
    scum[4 * t + 1] = pref + c1;
    scum[4 * t + 2] = pref + c2;
    scum[4 * t + 3] = pref + c3;
    __syncthreads();

    float total = scum[1022];
    if (t == 0) sg[0] = 0.0f;
    #pragma unroll
    for (int j = 0; j < 4; j++) {
        int idx = 4 * t + j;
        if (idx < 1022)       sg[idx + 1] = scum[idx] / total;
        else if (idx == 1022) sg[1023]    = 1.0f;
    }
    __syncthreads();

    #pragma unroll
    for (int j = 0; j < 4; j++) {
        int idx = 4 * t + j;
        if (idx < NCELL) {
            float xi  = sg[idx];
            float rdx = 1.0f / fmaxf(sg[idx + 1] - xi, EPSV);
            cells[idx] = make_float2(xi, rdx);
        }
    }
}

__global__ __launch_bounds__(BLOCK_T)
void build_all(const float* __restrict__ incx,
               const float* __restrict__ incy,
               const float* __restrict__ u) {
    int bx = blockIdx.x;
    if (bx < NX - 1) {
        const float* r0 = u + bx * NX;
        const float* r1 = r0 + NX;
        float4* qrow = g_quad + (bx << 10);
        for (int iy = threadIdx.x; iy < NX - 1; iy += BLOCK_T) {
            float4 q;
            q.x = r0[iy];
            q.y = r1[iy];
            q.z = r0[iy + 1];
            q.w = r1[iy + 1];
            qrow[iy] = q;
        }
    } else if (bx == NX - 1) {
        build_one_grid(incx, g_cellx);
    } else {
        build_one_grid(incy, g_celly);
    }
}

// ---------------------------------------------------------------------------
// Eval: persistent, 2-point groups, 2-STAGE gather pipeline — gathers for
// group k are consumed at k+2 (~360 cyc program-order slack, covering loaded
// L2 latency). Lazy-probe locate (minimal avg LDS bytes per R9).
// ---------------------------------------------------------------------------
__device__ __forceinline__ int locate(float x, const float2* __restrict__ sc,
                                      float& t) {
    int i = min(max(__float2int_rd(x * 1023.0f), 0), NCELL - 1);
    float2 c = sc[i];
    t = (x - c.x) * c.y;
    while (t < 0.0f && i > 0)            { c = sc[--i]; t = (x - c.x) * c.y; }
    while (t >= 1.0f && i < NCELL - 1)   { c = sc[++i]; t = (x - c.x) * c.y; }
    return i;
}

__device__ __forceinline__ float blend(float tx, float ty, float4 q) {
    float a = fmaf(tx, q.y - q.x, q.x);
    float b = fmaf(tx, q.w - q.z, q.z);
    return fmaf(ty, b - a, a);
}

// locate+gather one 2-point group; returns gathered quads + weights
__device__ __forceinline__ void stage(float4 a,
                                      const float2* __restrict__ scx,
                                      const float2* __restrict__ scy,
                                      float4& qa, float4& qb,
                                      float& tx0, float& ty0,
                                      float& tx1, float& ty1) {
    int ix0 = locate(a.x, scx, tx0);
    int iy0 = locate(a.y, scy, ty0);
    int ix1 = locate(a.z, scx, tx1);
    int iy1 = locate(a.w, scy, ty1);
    qa = __ldg(&g_quad[(ix0 << 10) + iy0]);
    qb = __ldg(&g_quad[(ix1 << 10) + iy1]);
}

__global__ __launch_bounds__(BLOCK_T, EVAL_MINBLK)
void eval_kernel(const float4* __restrict__ xe4, float2* __restrict__ out2,
                 const float2* __restrict__ xe2, float* __restrict__ outs,
                 int n) {
    __shared__ float2 scx[NCELL];
    __shared__ float2 scy[NCELL];
    for (int i = threadIdx.x; i < NCELL; i += BLOCK_T) {
        scx[i] = g_cellx[i];
        scy[i] = g_celly[i];
    }
    __syncthreads();

    const int ngroups = n >> 1;                  // 2-point groups
    const int stride  = gridDim.x * BLOCK_T;
    const int glast   = ngroups - 1;

    int g0 = blockIdx.x * BLOCK_T + threadIdx.x;
    if (g0 < ngroups) {
        int niter = (ngroups - 1 - g0) / stride + 1;

        // ---- prologue: fill stages for groups 0 and 1 ----
        float4 q0a, q0b, q1a, q1b;
        float tA0, tA1, tA2, tA3;   // weights for stage 0
        float tB0, tB1, tB2, tB3;   // weights for stage 1

        float4 a = __ldcs(&xe4[g0]);
        stage(a, scx, scy, q0a, q0b, tA0, tA1, tA2, tA3);

        a = __ldcs(&xe4[min(g0 + stride, glast)]);   // clamped (unused if niter==1)
        stage(a, scx, scy, q1a, q1b, tB0, tB1, tB2, tB3);

        // ---- steady state: issue k, retire k-2 ----
        #pragma unroll 1
        for (int k = 2; k < niter; k++) {
            int gk = g0 + k * stride;
            a = __ldcs(&xe4[gk]);

            float4 nqa, nqb;
            float nt0, nt1, nt2, nt3;
            stage(a, scx, scy, nqa, nqb, nt0, nt1, nt2, nt3);

            float2 r;
            r.x = blend(tA0, tA1, q0a);
            r.y = blend(tA2, tA3, q0b);
            __stcs(&out2[gk - 2 * stride], r);

            q0a = q1a; q0b = q1b;
            tA0 = tB0; tA1 = tB1; tA2 = tB2; tA3 = tB3;
            q1a = nqa; q1b = nqb;
            tB0 = nt0; tB1 = nt1; tB2 = nt2; tB3 = nt3;
        }

        // ---- epilogue: drain pending stages ----
        if (niter == 1) {
            float2 r;
            r.x = blend(tA0, tA1, q0a);
            r.y = blend(tA2, tA3, q0b);
            __stcs(&out2[g0], r);
        } else {
            float2 r;
            r.x = blend(tA0, tA1, q0a);
            r.y = blend(tA2, tA3, q0b);
            __stcs(&out2[g0 + (niter - 2) * stride], r);
            r.x = blend(tB0, tB1, q1a);
            r.y = blend(tB2, tB3, q1b);
            __stcs(&out2[g0 + (niter - 1) * stride], r);
        }
    }

    // scalar tail (never runs when n % 2 == 0, e.g. n = 8,000,000)
    int tail = (n >> 1) << 1;
    if (blockIdx.x == 0) {
        for (int i = tail + threadIdx.x; i < n; i += BLOCK_T) {
            float2 p = xe2[i];
            float tx, ty;
            int ixx = locate(p.x, scx, tx);
            int iyy = locate(p.y, scy, ty);
            float4 q = __ldg(&g_quad[(ixx << 10) + iyy]);
            outs[i] = blend(tx, ty, q);
        }
    }
}

// ---------------------------------------------------------------------------
extern "C" void kernel_launch(void* const* d_in, const int* in_sizes, int n_in,
                              void* d_out, int out_size) {
    const float* xe   = (const float*)d_in[0];
    const float* incx = (const float*)d_in[1];
    const float* incy = (const float*)d_in[2];
    const float* u    = (const float*)d_in[3];
    int n = out_size;   // 8,000,000

    build_all<<<(NX - 1) + 2, BLOCK_T>>>(incx, incy, u);

    eval_kernel<<<EVAL_BLOCKS, BLOCK_T>>>((const float4*)xe, (float2*)d_out,
                                          (const float2*)xe, (float*)d_out, n);
}

// round 15
// speedup vs baseline: 1.2234x; 1.2234x over previous
#include <cuda_runtime.h>
#include <cuda_bf16.h>

#define NX 1024
#define NCELL 1023
#define EPSV 1e-10f
#define BLOCK_T 256
#define EVAL_MINBLK 8
#define EVAL_BLOCKS (EVAL_MINBLK * 148)   // one persistent wave at 8 blocks/SM

// Scratch (__device__ globals — allocation-free rule)
__device__ float2 g_cellx[NCELL];           // (x_i, 1/max(dx,EPS)) per cell
__device__ float2 g_celly[NCELL];
__device__ float4 g_quad[(NX - 1) * NX];    // {u00,u10,u01,u11} per cell (ix<<10 | iy)

// ---------------------------------------------------------------------------
// Builder (unchanged)
// ---------------------------------------------------------------------------
__device__ __forceinline__ void build_one_grid(const float* __restrict__ inc,
                                               float2* __restrict__ cells) {
    __shared__ float scum[1024];
    __shared__ float sg[1024];
    __shared__ float swarp[8];

    const int t    = threadIdx.x;       // 0..255
    const int lane = t & 31;
    const int warp = t >> 5;

    float v[4];
    #pragma unroll
    for (int j = 0; j < 4; j++) {
        int idx = 4 * t + j;
        float val = 0.0f;
        if (idx < 1023) {
            float xv = inc[idx];
            float sp = fmaxf(xv, 0.0f) + log1pf(expf(-fabsf(xv)));  // softplus
            val = fmaxf(sp, 1e-6f);
        }
        v[j] = val;
    }
    float c0 = v[0];
    float c1 = c0 + v[1];
    float c2 = c1 + v[2];
    float c3 = c2 + v[3];

    float incl = c3;
    #pragma unroll
    for (int off = 1; off < 32; off <<= 1) {
        float up = __shfl_up_sync(0xffffffff, incl, off);
        if (lane >= off) incl += up;
    }
    float thr_excl = incl - c3;
    if (lane == 31) swarp[warp] = incl;
    __syncthreads();

    if (warp == 0 && lane < 8) {
        float w = swarp[lane];
        #pragma unroll
        for (int off = 1; off < 8; off <<= 1) {
            float up = __shfl_up_sync(0xff, w, off);
            if (lane >= off) w += up;
        }
        swarp[lane] = w - swarp[lane];
    }
    __syncthreads();

    float pref = swarp[warp] + thr_excl;
    scum[4 * t + 0] = pref + c0;
    scum[4 * t + 1] = pref + c1;
    scum[4 * t + 2] = pref + c2;
    scum[4 * t + 3] = pref + c3;
    __syncthreads();

    float total = scum[1022];
    if (t == 0) sg[0] = 0.0f;
    #pragma unroll
    for (int j = 0; j < 4; j++) {
        int idx = 4 * t + j;
        if (idx < 1022)       sg[idx + 1] = scum[idx] / total;
        else if (idx == 1022) sg[1023]    = 1.0f;
    }
    __syncthreads();

    #pragma unroll
    for (int j = 0; j < 4; j++) {
        int idx = 4 * t + j;
        if (idx < NCELL) {
            float xi  = sg[idx];
            float rdx = 1.0f / fmaxf(sg[idx + 1] - xi, EPSV);
            cells[idx] = make_float2(xi, rdx);
        }
    }
}

__global__ __launch_bounds__(BLOCK_T)
void build_all(const float* __restrict__ incx,
               const float* __restrict__ incy,
               const float* __restrict__ u) {
    int bx = blockIdx.x;
    if (bx < NX - 1) {
        const float* r0 = u + bx * NX;
        const float* r1 = r0 + NX;
        float4* qrow = g_quad + (bx << 10);
        for (int iy = threadIdx.x; iy < NX - 1; iy += BLOCK_T) {
            float4 q;
            q.x = r0[iy];
            q.y = r1[iy];
            q.z = r0[iy + 1];
            q.w = r1[iy + 1];
            qrow[iy] = q;
        }
    } else if (bx == NX - 1) {
        build_one_grid(incx, g_cellx);
    } else {
        build_one_grid(incy, g_celly);
    }
}

// ---------------------------------------------------------------------------
// Eval: persistent, ONE point per thread per iteration, 2-stage gather
// pipeline + 1-ahead xe prefetch. Carried state: q0/t0 (retiring), q1/t1
// (in flight), current coords, prefetched coords — fits 32 regs -> 8 blk/SM.
// Gathers are consumed two full iterations after issue (~2x body latency
// slack) while 64 warps/SM multiplex the remainder.
// ---------------------------------------------------------------------------
__device__ __forceinline__ int locate(float x, const float2* __restrict__ sc,
                                      float& t) {
    int i = min(max(__float2int_rd(x * 1023.0f), 0), NCELL - 1);
    float2 c = sc[i];
    t = (x - c.x) * c.y;
    while (t < 0.0f && i > 0)            { c = sc[--i]; t = (x - c.x) * c.y; }
    while (t >= 1.0f && i < NCELL - 1)   { c = sc[++i]; t = (x - c.x) * c.y; }
    return i;
}

__device__ __forceinline__ float blend(float tx, float ty, float4 q) {
    float a = fmaf(tx, q.y - q.x, q.x);
    float b = fmaf(tx, q.w - q.z, q.z);
    return fmaf(ty, b - a, a);
}

// locate both dims of one point and issue its gather
__device__ __forceinline__ float4 stage1(float2 p,
                                         const float2* __restrict__ scx,
                                         const float2* __restrict__ scy,
                                         float& tx, float& ty) {
    int ix = locate(p.x, scx, tx);
    int iy = locate(p.y, scy, ty);
    return __ldg(&g_quad[(ix << 10) + iy]);
}

__global__ __launch_bounds__(BLOCK_T, EVAL_MINBLK)
void eval_kernel(const float2* __restrict__ xe2, float* __restrict__ outs,
                 int n) {
    __shared__ float2 scx[NCELL];
    __shared__ float2 scy[NCELL];
    for (int i = threadIdx.x; i < NCELL; i += BLOCK_T) {
        scx[i] = g_cellx[i];
        scy[i] = g_celly[i];
    }
    __syncthreads();

    const int stride = gridDim.x * BLOCK_T;
    const int glast  = n - 1;

    int g0 = blockIdx.x * BLOCK_T + threadIdx.x;
    if (g0 >= n) return;
    int niter = (n - 1 - g0) / stride + 1;

    // ---- prologue ----
    float4 q0, q1;
    float t0x, t0y, t1x, t1y;

    float2 p = __ldcs(&xe2[g0]);
    q0 = stage1(p, scx, scy, t0x, t0y);                       // group 0

    p = __ldcs(&xe2[min(g0 + stride, glast)]);
    q1 = stage1(p, scx, scy, t1x, t1y);                       // group 1

    p = __ldcs(&xe2[min(g0 + 2 * stride, glast)]);            // coords for group 2

    // ---- steady state: issue k, retire k-2 ----
    #pragma unroll 1
    for (int k = 2; k < niter; k++) {
        int gk = g0 + k * stride;

        // prefetch coords for next iteration (clamped, branch-free)
        float2 pf = __ldcs(&xe2[min(gk + stride, glast)]);

        // locate + issue gather for current group k
        float ntx, nty;
        float4 nq = stage1(p, scx, scy, ntx, nty);

        // retire group k-2 (its gather is two bodies old)
        __stcs(&outs[gk - 2 * stride], blend(t0x, t0y, q0));

        // shift pipeline
        q0 = q1;  t0x = t1x;  t0y = t1y;
        q1 = nq;  t1x = ntx;  t1y = nty;
        p = pf;
    }

    // ---- epilogue: drain ----
    if (niter == 1) {
        __stcs(&outs[g0], blend(t0x, t0y, q0));
    } else {
        __stcs(&outs[g0 + (niter - 2) * stride], blend(t0x, t0y, q0));
        __stcs(&outs[g0 + (niter - 1) * stride], blend(t1x, t1y, q1));
    }
}

// ---------------------------------------------------------------------------
extern "C" void kernel_launch(void* const* d_in, const int* in_sizes, int n_in,
                              void* d_out, int out_size) {
    const float* xe   = (const float*)d_in[0];
    const float* incx = (const float*)d_in[1];
    const float* incy = (const float*)d_in[2];
    const float* u    = (const float*)d_in[3];
    int n = out_size;   // 8,000,000

    build_all<<<(NX - 1) + 2, BLOCK_T>>>(incx, incy, u);

    eval_kernel<<<EVAL_BLOCKS, BLOCK_T>>>((const float2*)xe, (float*)d_out, n);
}

// round 16
// speedup vs baseline: 1.2697x; 1.0378x over previous
#include <cuda_runtime.h>
#include <cuda_bf16.h>

#define NX 1024
#define NCELL 1023
#define EPSV 1e-10f
#define BLOCK_T 256
#define EVAL_MINBLK 6
#define EVAL_BLOCKS (EVAL_MINBLK * 148)   // one persistent wave at 6 blocks/SM

// Scratch (__device__ globals — allocation-free rule)
__device__ float2 g_cellx[NCELL];           // (x_i, 1/max(dx,EPS)) per cell
__device__ float2 g_celly[NCELL];
__device__ float4 g_quad[(NX - 1) * NX];    // {u00,u10,u01,u11} per cell (ix<<10 | iy)

// ---------------------------------------------------------------------------
// Builder (unchanged)
// ---------------------------------------------------------------------------
__device__ __forceinline__ void build_one_grid(const float* __restrict__ inc,
                                               float2* __restrict__ cells) {
    __shared__ float scum[1024];
    __shared__ float sg[1024];
    __shared__ float swarp[8];

    const int t    = threadIdx.x;       // 0..255
    const int lane = t & 31;
    const int warp = t >> 5;

    float v[4];
    #pragma unroll
    for (int j = 0; j < 4; j++) {
        int idx = 4 * t + j;
        float val = 0.0f;
        if (idx < 1023) {
            float xv = inc[idx];
            float sp = fmaxf(xv, 0.0f) + log1pf(expf(-fabsf(xv)));  // softplus
            val = fmaxf(sp, 1e-6f);
        }
        v[j] = val;
    }
    float c0 = v[0];
    float c1 = c0 + v[1];
    float c2 = c1 + v[2];
    float c3 = c2 + v[3];

    float incl = c3;
    #pragma unroll
    for (int off = 1; off < 32; off <<= 1) {
        float up = __shfl_up_sync(0xffffffff, incl, off);
        if (lane >= off) incl += up;
    }
    float thr_excl = incl - c3;
    if (lane == 31) swarp[warp] = incl;
    __syncthreads();

    if (warp == 0 && lane < 8) {
        float w = swarp[lane];
        #pragma unroll
        for (int off = 1; off < 8; off <<= 1) {
            float up = __shfl_up_sync(0xff, w, off);
            if (lane >= off) w += up;
        }
        swarp[lane] = w - swarp[lane];
    }
    __syncthreads();

    float pref = swarp[warp] + thr_excl;
    scum[4 * t + 0] = pref + c0;
    scum[4 * t + 1] = pref + c1;
    scum[4 * t + 2] = pref + c2;
    scum[4 * t + 3] = pref + c3;
    __syncthreads();

    float total = scum[1022];
    if (t == 0) sg[0] = 0.0f;
    #pragma unroll
    for (int j = 0; j < 4; j++) {
        int idx = 4 * t + j;
        if (idx < 1022)       sg[idx + 1] = scum[idx] / total;
        else if (idx == 1022) sg[1023]    = 1.0f;
    }
    __syncthreads();

    #pragma unroll
    for (int j = 0; j < 4; j++) {
        int idx = 4 * t + j;
        if (idx < NCELL) {
            float xi  = sg[idx];
            float rdx = 1.0f / fmaxf(sg[idx + 1] - xi, EPSV);
            cells[idx] = make_float2(xi, rdx);
        }
    }
}

__global__ __launch_bounds__(BLOCK_T)
void build_all(const float* __restrict__ incx,
               const float* __restrict__ incy,
               const float* __restrict__ u) {
    int bx = blockIdx.x;
    if (bx < NX - 1) {
        const float* r0 = u + bx * NX;
        const float* r1 = r0 + NX;
        float4* qrow = g_quad + (bx << 10);
        for (int iy = threadIdx.x; iy < NX - 1; iy += BLOCK_T) {
            float4 q;
            q.x = r0[iy];
            q.y = r1[iy];
            q.z = r0[iy + 1];
            q.w = r1[iy + 1];
            qrow[iy] = q;
        }
    } else if (bx == NX - 1) {
        build_one_grid(incx, g_cellx);
    } else {
        build_one_grid(incy, g_celly);
    }
}

// ---------------------------------------------------------------------------
// Eval: persistent, 1 point per pipeline step, 2-stage gather pipeline,
// HAND-UNROLLED x2 (two steps per loop trip): register rotation is done by
// the unroll (no shift MOVs), loop control amortized, xe prefetched 2 ahead.
// ---------------------------------------------------------------------------
__device__ __forceinline__ int locate(float x, const float2* __restrict__ sc,
                                      float& t) {
    int i = min(max(__float2int_rd(x * 1023.0f), 0), NCELL - 1);
    float2 c = sc[i];
    t = (x - c.x) * c.y;
    while (t < 0.0f && i > 0)            { c = sc[--i]; t = (x - c.x) * c.y; }
    while (t >= 1.0f && i < NCELL - 1)   { c = sc[++i]; t = (x - c.x) * c.y; }
    return i;
}

__device__ __forceinline__ float blend(float tx, float ty, float4 q) {
    float a = fmaf(tx, q.y - q.x, q.x);
    float b = fmaf(tx, q.w - q.z, q.z);
    return fmaf(ty, b - a, a);
}

// locate both dims of one point and issue its gather
__device__ __forceinline__ float4 stage1(float2 p,
                                         const float2* __restrict__ scx,
                                         const float2* __restrict__ scy,
                                         float& tx, float& ty) {
    int ix = locate(p.x, scx, tx);
    int iy = locate(p.y, scy, ty);
    return __ldg(&g_quad[(ix << 10) + iy]);
}

__global__ __launch_bounds__(BLOCK_T, EVAL_MINBLK)
void eval_kernel(const float2* __restrict__ xe2, float* __restrict__ outs,
                 int n) {
    __shared__ float2 scx[NCELL];
    __shared__ float2 scy[NCELL];
    for (int i = threadIdx.x; i < NCELL; i += BLOCK_T) {
        scx[i] = g_cellx[i];
        scy[i] = g_celly[i];
    }
    __syncthreads();

    const int stride = gridDim.x * BLOCK_T;
    const int glast  = n - 1;

    int g0 = blockIdx.x * BLOCK_T + threadIdx.x;
    if (g0 >= n) return;
    int niter = (n - 1 - g0) / stride + 1;

    // ---- prologue: issue steps 0 and 1, prefetch coords for steps 2,3 ----
    float4 q0, q1;
    float t0x, t0y, t1x, t1y;

    float2 p = __ldcs(&xe2[g0]);
    q0 = stage1(p, scx, scy, t0x, t0y);                        // step 0

    p = __ldcs(&xe2[min(g0 + stride, glast)]);
    q1 = stage1(p, scx, scy, t1x, t1y);                        // step 1

    float2 p2 = __ldcs(&xe2[min(g0 + 2 * stride, glast)]);     // coords step 2
    float2 p3 = __ldcs(&xe2[min(g0 + 3 * stride, glast)]);     // coords step 3

    int k = 2;

    // ---- steady state: two steps per trip (issue k,k+1; retire k-2,k-1) ----
    #pragma unroll 1
    while (k + 1 < niter) {
        int gk = g0 + k * stride;

        float2 pf0 = __ldcs(&xe2[min(gk + 2 * stride, glast)]);
        float2 pf1 = __ldcs(&xe2[min(gk + 3 * stride, glast)]);

        float t2x, t2y;
        float4 q2 = stage1(p2, scx, scy, t2x, t2y);            // issue step k
        __stcs(&outs[gk - 2 * stride], blend(t0x, t0y, q0));   // retire k-2

        float t3x, t3y;
        float4 q3 = stage1(p3, scx, scy, t3x, t3y);            // issue step k+1
        __stcs(&outs[gk - stride], blend(t1x, t1y, q1));       // retire k-1

        q0 = q2; t0x = t2x; t0y = t2y;
        q1 = q3; t1x = t3x; t1y = t3y;
        p2 = pf0; p3 = pf1;
        k += 2;
    }

    // ---- leftover single step (odd remaining) ----
    if (k < niter) {
        float t2x, t2y;
        float4 q2 = stage1(p2, scx, scy, t2x, t2y);            // issue step k
        __stcs(&outs[g0 + (k - 2) * stride], blend(t0x, t0y, q0));  // retire k-2
        q0 = q1; t0x = t1x; t0y = t1y;
        q1 = q2; t1x = t2x; t1y = t2y;
        k += 1;
    }

    // ---- drain: retire the last one or two in-flight steps ----
    if (niter == 1) {
        __stcs(&outs[g0], blend(t0x, t0y, q0));
    } else {
        __stcs(&outs[g0 + (niter - 2) * stride], blend(t0x, t0y, q0));
        __stcs(&outs[g0 + (niter - 1) * stride], blend(t1x, t1y, q1));
    }
}

// ---------------------------------------------------------------------------
extern "C" void kernel_launch(void* const* d_in, const int* in_sizes, int n_in,
                              void* d_out, int out_size) {
    const float* xe   = (const float*)d_in[0];
    const float* incx = (const float*)d_in[1];
    const float* incy = (const float*)d_in[2];
    const float* u    = (const float*)d_in[3];
    int n = out_size;   // 8,000,000

    build_all<<<(NX - 1) + 2, BLOCK_T>>>(incx, incy, u);

    eval_kernel<<<EVAL_BLOCKS, BLOCK_T>>>((const float2*)xe, (float*)d_out, n);
}